// round 17
// baseline (speedup 1.0000x reference)
#include <cuda_runtime.h>
#include <math.h>
#include <cstdint>

// Problem constants (fixed shapes from reference)
#define HW     3136     // 56*56
#define HW4    784      // HW / 4 (float4 chunks per row)
#define B_SZ   64
#define C_IN   512
#define A_DIM  32
#define C_OUT  512
#define BN_EPS 1e-5f

// fc smem layout (floats):
//   s_lin    : 512 rows x 36 words (32 data + 4 pad) = 18432 floats.
//              Padded row-major weight tile; stride 36 makes per-thread
//              LDS.128 row reads bank-conflict-free (each 8-lane phase
//              spans banks (4c+const)..+3, tiling all 32 banks).
//   s_pooled : 512
//   s_bias   : 512
//   s_bn     : 128  [gamma | beta | mean | var] x 32
//   s_h      : 32
#define ROW_STRIDE_W 36     // words per padded row
#define S_LIN_FLOATS (C_IN * ROW_STRIDE_W)
#define SMEM_FLOATS  (S_LIN_FLOATS + C_IN + C_IN + 128 + A_DIM)

// Scratch for pooled means: [B, C_in]
__device__ float g_pooled[B_SZ * C_IN];

__device__ __forceinline__ void cp_async16(uint32_t dst_smem, const void* src) {
    asm volatile("cp.async.cg.shared.global [%0], [%1], 16;"
                 :: "r"(dst_smem), "l"(src));
}

// ---------------------------------------------------------------------------
// Kernel 1: global average pool — UNCHANGED from R15/R16 (best measured:
// minimal streaming loop, 2-wide MLP, __ldcs evict-first). ~59us @ 7.1TB/s.
// Fusion / PDL / prefetch additions all measured as regressions; keep clean.
// ---------------------------------------------------------------------------
__global__ __launch_bounds__(256) void pool_kernel(const float* __restrict__ x) {
    const int gwarp = (blockIdx.x * blockDim.x + threadIdx.x) >> 5;
    const int lane  = threadIdx.x & 31;
    if (gwarp >= B_SZ * C_IN) return;

    const float4* __restrict__ row =
        reinterpret_cast<const float4*>(x + (size_t)gwarp * HW);

    float s0 = 0.f, s1 = 0.f;
    int i = lane;
    #pragma unroll 4
    for (; i + 32 < HW4; i += 64) {
        float4 v0 = __ldcs(&row[i]);        // streaming: evict-first
        float4 v1 = __ldcs(&row[i + 32]);
        s0 += (v0.x + v0.y) + (v0.z + v0.w);
        s1 += (v1.x + v1.y) + (v1.z + v1.w);
    }
    if (i < HW4) {
        float4 v0 = __ldcs(&row[i]);
        s0 += (v0.x + v0.y) + (v0.z + v0.w);
    }
    float s = s0 + s1;

    #pragma unroll
    for (int off = 16; off > 0; off >>= 1)
        s += __shfl_xor_sync(0xFFFFFFFFu, s, off);

    if (lane == 0)
        g_pooled[gwarp] = s * (1.0f / (float)HW);
}

// ---------------------------------------------------------------------------
// Kernel 2: FC chain. Grid = 128 blocks: block (b, t). 512 threads.
// Weight tile cp.async'd DIRECTLY into the padded conflict-free layout
// (no transpose — the R16 win). NEW: two commit groups. Group A (pooled +
// bn, L2-hot, fast) is waited on first so the h-stage runs while group B
// (weight tile + bias, DRAM-cold) is still filling; wait_group 0 gates
// only the final dot.
// ---------------------------------------------------------------------------
__global__ __launch_bounds__(512) void fc_kernel(
    const float* __restrict__ fc_w,         // [A, C_in]
    const float* __restrict__ bn_gamma,     // [A]
    const float* __restrict__ bn_beta,      // [A]
    const float* __restrict__ bn_mean,      // [A]
    const float* __restrict__ bn_var,       // [A]
    const float* __restrict__ channel_fc_w, // [C_in, A]
    const float* __restrict__ channel_fc_b, // [C_in]
    const float* __restrict__ filter_fc_w,  // [C_out, A]
    const float* __restrict__ filter_fc_b,  // [C_out]
    float* __restrict__ out)                // [2 * B * 512]
{
    extern __shared__ __align__(16) float smem[];
    float* s_lin    = smem;                           // 512 x 36
    float* s_pooled = smem + S_LIN_FLOATS;            // 512 (16B-aligned)
    float* s_bias   = s_pooled + C_IN;                // 512
    float* s_bn     = s_bias + C_IN;                  // 128
    float* s_h      = s_bn + 128;                     // 32

    const int b    = blockIdx.x >> 1;
    const int t    = blockIdx.x & 1;        // 0 = channel, 1 = filter
    const int tid  = threadIdx.x;
    const int warp = tid >> 5;
    const int lane = tid & 31;

    const float* __restrict__ w_mat  = t ? filter_fc_w : channel_fc_w;
    const float* __restrict__ w_bias = t ? filter_fc_b : channel_fc_b;

    // ---- fc_w rows for this warp's two h-dots: register loads, hoisted ----
    const int a0 = warp, a1 = warp + 16;
    const float4* __restrict__ f0 =
        reinterpret_cast<const float4*>(fc_w + a0 * C_IN);
    const float4* __restrict__ f1 =
        reinterpret_cast<const float4*>(fc_w + a1 * C_IN);
    float4 fw00 = __ldg(&f0[lane]);      float4 fw01 = __ldg(&f0[lane + 32]);
    float4 fw02 = __ldg(&f0[lane + 64]); float4 fw03 = __ldg(&f0[lane + 96]);
    float4 fw10 = __ldg(&f1[lane]);      float4 fw11 = __ldg(&f1[lane + 32]);
    float4 fw12 = __ldg(&f1[lane + 64]); float4 fw13 = __ldg(&f1[lane + 96]);

    const uint32_t s_lin_a    = (uint32_t)__cvta_generic_to_shared(s_lin);
    const uint32_t s_pooled_a = (uint32_t)__cvta_generic_to_shared(s_pooled);
    const uint32_t s_bias_a   = (uint32_t)__cvta_generic_to_shared(s_bias);
    const uint32_t s_bn_a     = (uint32_t)__cvta_generic_to_shared(s_bn);

    // ---- group A: pooled (L2-hot) + bn params — committed FIRST ----
    if (tid < 128) {
        cp_async16(s_pooled_a + tid * 16, g_pooled + b * C_IN + tid * 4);
    } else if (tid < 136) {
        const int j = tid - 128;
        cp_async16(s_bn_a + j * 16, bn_gamma + j * 4);          // [0,32)
    } else if (tid < 144) {
        const int j = tid - 136;
        cp_async16(s_bn_a + 128 + j * 16, bn_beta + j * 4);     // [32,64)
    } else if (tid < 152) {
        const int j = tid - 144;
        cp_async16(s_bn_a + 256 + j * 16, bn_mean + j * 4);     // [64,96)
    } else if (tid < 160) {
        const int j = tid - 152;
        cp_async16(s_bn_a + 384 + j * 16, bn_var + j * 4);      // [96,128)
    }
    asm volatile("cp.async.commit_group;");

    // ---- group B: weight tile (padded layout) + bias — DRAM-cold ----
    #pragma unroll
    for (int k = 0; k < 8; ++k) {
        const int i    = tid + k * 512;      // global float4 index (0..4095)
        const int row  = i >> 3;             // weight row (8 chunks per row)
        const int chnk = i & 7;              // 16B chunk within row
        cp_async16(s_lin_a + (row * ROW_STRIDE_W + chnk * 4) * 4,
                   w_mat + i * 4);
    }
    if (tid >= 384) {                        // warps 12-15: bias (128 chunks)
        const int j = tid - 384;
        cp_async16(s_bias_a + j * 16, w_bias + j * 4);
    }
    asm volatile("cp.async.commit_group;");

    // ---- wait for group A only (B may still be in flight) ----
    asm volatile("cp.async.wait_group 1;");
    __syncthreads();

    // ---- h: warp-parallel dots (fc_w in regs, pooled in smem) ----
    const float4* __restrict__ sp4 = reinterpret_cast<const float4*>(s_pooled);
    float4 pv0 = sp4[lane];      float4 pv1 = sp4[lane + 32];
    float4 pv2 = sp4[lane + 64]; float4 pv3 = sp4[lane + 96];

    float acc0 = 0.f, acc1 = 0.f;
    acc0 = fmaf(fw00.x, pv0.x, acc0); acc0 = fmaf(fw00.y, pv0.y, acc0);
    acc0 = fmaf(fw00.z, pv0.z, acc0); acc0 = fmaf(fw00.w, pv0.w, acc0);
    acc0 = fmaf(fw01.x, pv1.x, acc0); acc0 = fmaf(fw01.y, pv1.y, acc0);
    acc0 = fmaf(fw01.z, pv1.z, acc0); acc0 = fmaf(fw01.w, pv1.w, acc0);
    acc0 = fmaf(fw02.x, pv2.x, acc0); acc0 = fmaf(fw02.y, pv2.y, acc0);
    acc0 = fmaf(fw02.z, pv2.z, acc0); acc0 = fmaf(fw02.w, pv2.w, acc0);
    acc0 = fmaf(fw03.x, pv3.x, acc0); acc0 = fmaf(fw03.y, pv3.y, acc0);
    acc0 = fmaf(fw03.z, pv3.z, acc0); acc0 = fmaf(fw03.w, pv3.w, acc0);

    acc1 = fmaf(fw10.x, pv0.x, acc1); acc1 = fmaf(fw10.y, pv0.y, acc1);
    acc1 = fmaf(fw10.z, pv0.z, acc1); acc1 = fmaf(fw10.w, pv0.w, acc1);
    acc1 = fmaf(fw11.x, pv1.x, acc1); acc1 = fmaf(fw11.y, pv1.y, acc1);
    acc1 = fmaf(fw11.z, pv1.z, acc1); acc1 = fmaf(fw11.w, pv1.w, acc1);
    acc1 = fmaf(fw12.x, pv2.x, acc1); acc1 = fmaf(fw12.y, pv2.y, acc1);
    acc1 = fmaf(fw12.z, pv2.z, acc1); acc1 = fmaf(fw12.w, pv2.w, acc1);
    acc1 = fmaf(fw13.x, pv3.x, acc1); acc1 = fmaf(fw13.y, pv3.y, acc1);
    acc1 = fmaf(fw13.z, pv3.z, acc1); acc1 = fmaf(fw13.w, pv3.w, acc1);

    #pragma unroll
    for (int off = 16; off > 0; off >>= 1) {
        acc0 += __shfl_xor_sync(0xFFFFFFFFu, acc0, off);
        acc1 += __shfl_xor_sync(0xFFFFFFFFu, acc1, off);
    }
    if (lane == 0) {
        // BN folded: h = (acc - mean) * (gamma * rsqrt(var+eps)) + beta
        float sc0 = s_bn[a0] * rsqrtf(s_bn[96 + a0] + BN_EPS);
        float sc1 = s_bn[a1] * rsqrtf(s_bn[96 + a1] + BN_EPS);
        float h0 = fmaf(acc0 - s_bn[64 + a0], sc0, s_bn[32 + a0]);
        float h1 = fmaf(acc1 - s_bn[64 + a1], sc1, s_bn[32 + a1]);
        s_h[a0] = fmaxf(h0, 0.f);
        s_h[a1] = fmaxf(h1, 0.f);
    }

    // ---- now require the weight tile + bias (group B) ----
    asm volatile("cp.async.wait_group 0;");
    __syncthreads();

    // ---- attention output: thread c reads its padded weight row via 8
    //      conflict-free LDS.128 (row stride 9 float4) and dots with s_h ----
    const float4* __restrict__ sl4 = reinterpret_cast<const float4*>(s_lin);
    float acc = s_bias[tid];
    #pragma unroll
    for (int j = 0; j < 8; ++j) {
        float4 wv = sl4[tid * (ROW_STRIDE_W / 4) + j];
        acc = fmaf(s_h[4 * j + 0], wv.x, acc);
        acc = fmaf(s_h[4 * j + 1], wv.y, acc);
        acc = fmaf(s_h[4 * j + 2], wv.z, acc);
        acc = fmaf(s_h[4 * j + 3], wv.w, acc);
    }

    // fast sigmoid (MUFU.EX2 + fast rcp): rel err ~1e-7, budget 1e-3
    out[(size_t)t * (B_SZ * C_IN) + b * C_IN + tid] =
        __fdividef(1.0f, 1.0f + __expf(-acc));
}

extern "C" void kernel_launch(void* const* d_in, const int* in_sizes, int n_in,
                              void* d_out, int out_size) {
    const float* x            = (const float*)d_in[0];
    const float* fc_w         = (const float*)d_in[1];
    const float* bn_gamma     = (const float*)d_in[2];
    const float* bn_beta      = (const float*)d_in[3];
    const float* bn_mean      = (const float*)d_in[4];
    const float* bn_var       = (const float*)d_in[5];
    const float* channel_fc_w = (const float*)d_in[6];
    const float* channel_fc_b = (const float*)d_in[7];
    const float* filter_fc_w  = (const float*)d_in[8];
    const float* filter_fc_b  = (const float*)d_in[9];
    float* out = (float*)d_out;

    const int smem_bytes = SMEM_FLOATS * (int)sizeof(float);
    static bool attr_set = false;   // host-side only; idempotent runtime attr
    if (!attr_set) {
        cudaFuncSetAttribute(fc_kernel,
                             cudaFuncAttributeMaxDynamicSharedMemorySize,
                             smem_bytes);
        attr_set = true;
    }

    pool_kernel<<<(B_SZ * C_IN) / 8, 256>>>(x);

    fc_kernel<<<B_SZ * 2, 512, smem_bytes>>>(
        fc_w, bn_gamma, bn_beta, bn_mean, bn_var,
        channel_fc_w, channel_fc_b, filter_fc_w, filter_fc_b, out);
}